// round 7
// baseline (speedup 1.0000x reference)
#include <cuda_runtime.h>

// Problem constants (fixed by setup_inputs)
#define B_   4
#define H_   64
#define W_   96
#define CH_  1152      // K*K*128
#define C_   128
#define S_   6
#define IMW_ 1536.0f
#define IMH_ 1024.0f

// Block = 1 ROI, 256 threads = 8 warps.
// Warps split: group g = wz>>1 strides samples (4 groups), half h = wz&1
// picks channels [h*64, h*64+64). Each lane owns 2 channels (float2).
// Unroll x2 -> 8 independent LDG.64 in flight with only 16 data registers,
// allowing 5 CTAs/SM (48-reg cap) WITH 8-deep MLP per warp.

__global__ __launch_bounds__(256, 5) void rroi_kernel(
    const float* __restrict__ fm,
    const float* __restrict__ rois,
    float* __restrict__ out,
    int nroi)
{
    const int n = blockIdx.x;
    if (n >= nroi) return;

    const int tid  = threadIdx.x;
    const int wz   = tid >> 5;
    const int lane = tid & 31;

    // raw (uncompacted) descriptor tables
    __shared__ float tyw0[18], tyw1[18], txw0[18], txw1[18];
    __shared__ int   tyr0[18], tyr1[18], txc0[18], txc1[18];
    __shared__ int   tyv[18], txv[18];
    // compacted lists
    __shared__ int   cYr0[18], cYr1[18], cYch[18];
    __shared__ float cYw0[18], cYw1[18];
    __shared__ int   cXc0[18], cXc1[18], cXch[18];
    __shared__ float cXw0[18], cXw1[18];
    __shared__ int   sNy, sNx;
    // per-pair descriptors
    __shared__ int4   sOff[324];
    __shared__ float4 sWt[324];
    __shared__ float  part[8 * 64];   // 8 warps x 64 channels

    // ROI params (broadcast loads)
    const float rb  = rois[n * 5 + 0];
    const float rx1 = rois[n * 5 + 1];
    const float ry1 = rois[n * 5 + 2];
    const float rx2 = rois[n * 5 + 3];
    const float ry2 = rois[n * 5 + 4];

    const int   b   = (int)rb;
    const float bx1 = rx1 / IMW_;
    const float by1 = ry1 / IMH_;
    const float bx2 = rx2 / IMW_;
    const float by2 = ry2 / IMH_;

    const float bin_w = (bx2 - bx1) / 3.0f;
    const float bin_h = by2 - by1 / 3.0f;      // reference bug, replicated

    // Phase 1: 18 y-descriptors (threads 0-17), 18 x-descriptors (threads 64-81)
    if (tid < 18) {
        const int d  = tid;
        const int ih = d / 6;
        const int sy = d - ih * 6;
        const float cy1 = by1 + (float)ih * bin_h;
        const float cy2 = by1 + (float)(ih + 1) * bin_h;
        const float ysv = cy1 * (float)(H_ - 1)
                        + (float)sy * ((cy2 - cy1) * (float)(H_ - 1) / (float)(S_ - 1));
        const int valid = (ysv >= 0.0f) && (ysv <= (float)(H_ - 1));
        const float y0f = floorf(ysv);
        const float ly  = ysv - y0f;
        int i0 = (int)y0f;
        i0 = i0 < 0 ? 0 : (i0 > H_ - 1 ? H_ - 1 : i0);
        int i1 = i0 + 1 > H_ - 1 ? H_ - 1 : i0 + 1;
        tyv[d]  = valid;
        tyr0[d] = i0 * (W_ * CH_);
        tyr1[d] = i1 * (W_ * CH_);
        tyw0[d] = 1.0f - ly;
        tyw1[d] = ly;
    } else if (tid >= 64 && tid < 82) {
        const int d  = tid - 64;
        const int iw = d / 6;
        const int sx = d - iw * 6;
        const float cx1 = bx1 + (float)iw * bin_w;
        const float cx2 = bx1 + (float)(iw + 1) * bin_h;   // reference bug, replicated
        const float xsv = cx1 * (float)(W_ - 1)
                        + (float)sx * ((cx2 - cx1) * (float)(W_ - 1) / (float)(S_ - 1));
        const int valid = (xsv >= 0.0f) && (xsv <= (float)(W_ - 1));
        const float x0f = floorf(xsv);
        const float lx  = xsv - x0f;
        int i0 = (int)x0f;
        i0 = i0 < 0 ? 0 : (i0 > W_ - 1 ? W_ - 1 : i0);
        int i1 = i0 + 1 > W_ - 1 ? W_ - 1 : i0 + 1;
        txv[d]  = valid;
        txc0[d] = i0 * CH_;
        txc1[d] = i1 * CH_;
        txw0[d] = 1.0f - lx;
        txw1[d] = lx;
    }
    __syncthreads();

    // Phase 2: compact valid descriptors (two threads in different warps)
    if (tid == 0) {
        int c = 0;
        #pragma unroll
        for (int d = 0; d < 18; ++d) {
            if (tyv[d]) {
                cYr0[c] = tyr0[d];
                cYr1[c] = tyr1[d];
                cYw0[c] = tyw0[d];
                cYw1[c] = tyw1[d];
                cYch[c] = (d / 6) * (3 * C_);   // ih*3*C
                ++c;
            }
        }
        sNy = c;
    } else if (tid == 32) {
        int c = 0;
        #pragma unroll
        for (int d = 0; d < 18; ++d) {
            if (txv[d]) {
                cXc0[c] = txc0[d];
                cXc1[c] = txc1[d];
                cXw0[c] = txw0[d];
                cXw1[c] = txw1[d];
                cXch[c] = (d / 6) * C_;         // iw*C
                ++c;
            }
        }
        sNx = c;
    }
    __syncthreads();

    const int ny = sNy, nx = sNx;
    const int total = ny * nx;

    // Phase 3: build per-pair descriptors
    for (int p = tid; p < total; p += 256) {
        const int yi = p / nx;
        const int xi = p - yi * nx;
        const int chb = cYch[yi] + cXch[xi];
        const int r0 = cYr0[yi], r1 = cYr1[yi];
        const int cA = cXc0[xi], cB = cXc1[xi];
        int4 o;
        o.x = r0 + cA + chb;
        o.y = r0 + cB + chb;
        o.z = r1 + cA + chb;
        o.w = r1 + cB + chb;
        sOff[p] = o;
        const float wy0 = cYw0[yi], wy1 = cYw1[yi];
        const float wx0 = cXw0[xi], wx1 = cXw1[xi];
        sWt[p] = make_float4(wy0 * wx0, wy0 * wx1, wy1 * wx0, wy1 * wx1);
    }
    __syncthreads();

    // Main loop: group g strides samples by 4 (unroll x2 -> stride 8);
    // half h picks 64 channels; lane owns 2 channels.
    const int g = wz >> 1;
    const int h = wz & 1;
    const float* pb = fm + (size_t)b * (H_ * W_ * CH_) + h * 64 + lane * 2;

    float2 acc0 = make_float2(0.0f, 0.0f);
    float2 acc1 = make_float2(0.0f, 0.0f);

    int p = g;
    for (; p + 4 < total; p += 8) {
        const int4   oA = sOff[p];
        const int4   oB = sOff[p + 4];
        const float4 wA = sWt[p];
        const float4 wB = sWt[p + 4];

        // 8 independent LDG.64 in flight (16 data regs)
        const float2 a00 = *(const float2*)(pb + oA.x);
        const float2 a01 = *(const float2*)(pb + oA.y);
        const float2 a10 = *(const float2*)(pb + oA.z);
        const float2 a11 = *(const float2*)(pb + oA.w);
        const float2 b00 = *(const float2*)(pb + oB.x);
        const float2 b01 = *(const float2*)(pb + oB.y);
        const float2 b10 = *(const float2*)(pb + oB.z);
        const float2 b11 = *(const float2*)(pb + oB.w);

        acc0.x += wA.x * a00.x + wA.y * a01.x + wA.z * a10.x + wA.w * a11.x;
        acc0.y += wA.x * a00.y + wA.y * a01.y + wA.z * a10.y + wA.w * a11.y;

        acc1.x += wB.x * b00.x + wB.y * b01.x + wB.z * b10.x + wB.w * b11.x;
        acc1.y += wB.x * b00.y + wB.y * b01.y + wB.z * b10.y + wB.w * b11.y;
    }
    if (p < total) {
        const int4   o = sOff[p];
        const float4 w = sWt[p];
        const float2 f00 = *(const float2*)(pb + o.x);
        const float2 f01 = *(const float2*)(pb + o.y);
        const float2 f10 = *(const float2*)(pb + o.z);
        const float2 f11 = *(const float2*)(pb + o.w);
        acc0.x += w.x * f00.x + w.y * f01.x + w.z * f10.x + w.w * f11.x;
        acc0.y += w.x * f00.y + w.y * f01.y + w.z * f10.y + w.w * f11.y;
    }

    acc0.x += acc1.x;
    acc0.y += acc1.y;

    // Deterministic reduction: part[warp][64 channels]
    ((float2*)part)[wz * 32 + lane] = acc0;
    __syncthreads();

    if (tid < C_) {
        const int hh = tid >> 6;          // channel half
        const int cc = tid & 63;          // channel within half
        float ssum = part[(hh    ) * 64 + cc]
                   + part[(hh + 2) * 64 + cc]
                   + part[(hh + 4) * 64 + cc]
                   + part[(hh + 6) * 64 + cc];
        out[n * C_ + tid] = ssum * (1.0f / 324.0f);
    }
}

extern "C" void kernel_launch(void* const* d_in, const int* in_sizes, int n_in,
                              void* d_out, int out_size) {
    const float* fm   = (const float*)d_in[0];
    const float* rois = (const float*)d_in[1];
    float* out        = (float*)d_out;
    const int nroi    = in_sizes[1] / 5;

    rroi_kernel<<<nroi, 256>>>(fm, rois, out, nroi);
}

// round 8
// speedup vs baseline: 1.1636x; 1.1636x over previous
#include <cuda_runtime.h>

// Problem constants (fixed by setup_inputs)
#define B_   4
#define H_   64
#define W_   96
#define CH_  1152      // K*K*128
#define C_   128
#define S_   6
#define IMW_ 1536.0f
#define IMH_ 1024.0f

// Block = 1 ROI, 256 threads = 8 warps; each lane owns 4 channels (float4).
// Setup compacts valid y/x descriptors, pre-bakes per-pair descriptors in SMEM.
// Main loop unrolled x3: 12 independent LDG.128 in flight per warp.

__global__ __launch_bounds__(256, 3) void rroi_kernel(
    const float* __restrict__ fm,
    const float* __restrict__ rois,
    float* __restrict__ out,
    int nroi)
{
    const int n = blockIdx.x;
    if (n >= nroi) return;

    const int tid  = threadIdx.x;
    const int wz   = tid >> 5;
    const int lane = tid & 31;

    // raw (uncompacted) descriptor tables
    __shared__ float tyw0[18], tyw1[18], txw0[18], txw1[18];
    __shared__ int   tyr0[18], tyr1[18], txc0[18], txc1[18];
    __shared__ int   tyv[18], txv[18];
    // compacted lists
    __shared__ int   cYr0[18], cYr1[18], cYch[18];
    __shared__ float cYw0[18], cYw1[18];
    __shared__ int   cXc0[18], cXc1[18], cXch[18];
    __shared__ float cXw0[18], cXw1[18];
    __shared__ int   sNy, sNx;
    // per-pair descriptors
    __shared__ int4   sOff[324];
    __shared__ float4 sWt[324];
    __shared__ float  part[8 * C_];

    // ROI params (broadcast loads)
    const float rb  = rois[n * 5 + 0];
    const float rx1 = rois[n * 5 + 1];
    const float ry1 = rois[n * 5 + 2];
    const float rx2 = rois[n * 5 + 3];
    const float ry2 = rois[n * 5 + 4];

    const int   b   = (int)rb;
    const float bx1 = rx1 / IMW_;
    const float by1 = ry1 / IMH_;
    const float bx2 = rx2 / IMW_;
    const float by2 = ry2 / IMH_;

    const float bin_w = (bx2 - bx1) / 3.0f;
    const float bin_h = by2 - by1 / 3.0f;      // reference bug, replicated

    // Phase 1: 18 y-descriptors (threads 0-17), 18 x-descriptors (threads 64-81)
    if (tid < 18) {
        const int d  = tid;
        const int ih = d / 6;
        const int sy = d - ih * 6;
        const float cy1 = by1 + (float)ih * bin_h;
        const float cy2 = by1 + (float)(ih + 1) * bin_h;
        const float ysv = cy1 * (float)(H_ - 1)
                        + (float)sy * ((cy2 - cy1) * (float)(H_ - 1) / (float)(S_ - 1));
        const int valid = (ysv >= 0.0f) && (ysv <= (float)(H_ - 1));
        const float y0f = floorf(ysv);
        const float ly  = ysv - y0f;
        int i0 = (int)y0f;
        i0 = i0 < 0 ? 0 : (i0 > H_ - 1 ? H_ - 1 : i0);
        int i1 = i0 + 1 > H_ - 1 ? H_ - 1 : i0 + 1;
        tyv[d]  = valid;
        tyr0[d] = i0 * (W_ * CH_);
        tyr1[d] = i1 * (W_ * CH_);
        tyw0[d] = 1.0f - ly;
        tyw1[d] = ly;
    } else if (tid >= 64 && tid < 82) {
        const int d  = tid - 64;
        const int iw = d / 6;
        const int sx = d - iw * 6;
        const float cx1 = bx1 + (float)iw * bin_w;
        const float cx2 = bx1 + (float)(iw + 1) * bin_h;   // reference bug, replicated
        const float xsv = cx1 * (float)(W_ - 1)
                        + (float)sx * ((cx2 - cx1) * (float)(W_ - 1) / (float)(S_ - 1));
        const int valid = (xsv >= 0.0f) && (xsv <= (float)(W_ - 1));
        const float x0f = floorf(xsv);
        const float lx  = xsv - x0f;
        int i0 = (int)x0f;
        i0 = i0 < 0 ? 0 : (i0 > W_ - 1 ? W_ - 1 : i0);
        int i1 = i0 + 1 > W_ - 1 ? W_ - 1 : i0 + 1;
        txv[d]  = valid;
        txc0[d] = i0 * CH_;
        txc1[d] = i1 * CH_;
        txw0[d] = 1.0f - lx;
        txw1[d] = lx;
    }
    __syncthreads();

    // Phase 2: compact valid descriptors (two threads in different warps)
    if (tid == 0) {
        int c = 0;
        #pragma unroll
        for (int d = 0; d < 18; ++d) {
            if (tyv[d]) {
                cYr0[c] = tyr0[d];
                cYr1[c] = tyr1[d];
                cYw0[c] = tyw0[d];
                cYw1[c] = tyw1[d];
                cYch[c] = (d / 6) * (3 * C_);   // ih*3*C
                ++c;
            }
        }
        sNy = c;
    } else if (tid == 32) {
        int c = 0;
        #pragma unroll
        for (int d = 0; d < 18; ++d) {
            if (txv[d]) {
                cXc0[c] = txc0[d];
                cXc1[c] = txc1[d];
                cXw0[c] = txw0[d];
                cXw1[c] = txw1[d];
                cXch[c] = (d / 6) * C_;         // iw*C
                ++c;
            }
        }
        sNx = c;
    }
    __syncthreads();

    const int ny = sNy, nx = sNx;
    const int total = ny * nx;

    // Phase 3: build per-pair descriptors
    for (int p = tid; p < total; p += 256) {
        const int yi = p / nx;
        const int xi = p - yi * nx;
        const int chb = cYch[yi] + cXch[xi];
        const int r0 = cYr0[yi], r1 = cYr1[yi];
        const int cA = cXc0[xi], cB = cXc1[xi];
        int4 o;
        o.x = r0 + cA + chb;
        o.y = r0 + cB + chb;
        o.z = r1 + cA + chb;
        o.w = r1 + cB + chb;
        sOff[p] = o;
        const float wy0 = cYw0[yi], wy1 = cYw1[yi];
        const float wx0 = cXw0[xi], wx1 = cXw1[xi];
        sWt[p] = make_float4(wy0 * wx0, wy0 * wx1, wy1 * wx0, wy1 * wx1);
    }
    __syncthreads();

    // Main loop (unrolled x3): 8 warps stride the valid pairs.
    const float* pb = fm + (size_t)b * (H_ * W_ * CH_) + lane * 4;

    float4 acc0 = make_float4(0.0f, 0.0f, 0.0f, 0.0f);
    float4 acc1 = make_float4(0.0f, 0.0f, 0.0f, 0.0f);
    float4 acc2 = make_float4(0.0f, 0.0f, 0.0f, 0.0f);

    int p = wz;
    for (; p + 16 < total; p += 24) {
        const int4   oA = sOff[p];
        const int4   oB = sOff[p + 8];
        const int4   oC = sOff[p + 16];
        const float4 wA = sWt[p];
        const float4 wB = sWt[p + 8];
        const float4 wC = sWt[p + 16];

        // 12 independent LDG.128 in flight
        const float4 a00 = *(const float4*)(pb + oA.x);
        const float4 a01 = *(const float4*)(pb + oA.y);
        const float4 a10 = *(const float4*)(pb + oA.z);
        const float4 a11 = *(const float4*)(pb + oA.w);
        const float4 b00 = *(const float4*)(pb + oB.x);
        const float4 b01 = *(const float4*)(pb + oB.y);
        const float4 b10 = *(const float4*)(pb + oB.z);
        const float4 b11 = *(const float4*)(pb + oB.w);
        const float4 c00 = *(const float4*)(pb + oC.x);
        const float4 c01 = *(const float4*)(pb + oC.y);
        const float4 c10 = *(const float4*)(pb + oC.z);
        const float4 c11 = *(const float4*)(pb + oC.w);

        acc0.x += wA.x * a00.x + wA.y * a01.x + wA.z * a10.x + wA.w * a11.x;
        acc0.y += wA.x * a00.y + wA.y * a01.y + wA.z * a10.y + wA.w * a11.y;
        acc0.z += wA.x * a00.z + wA.y * a01.z + wA.z * a10.z + wA.w * a11.z;
        acc0.w += wA.x * a00.w + wA.y * a01.w + wA.z * a10.w + wA.w * a11.w;

        acc1.x += wB.x * b00.x + wB.y * b01.x + wB.z * b10.x + wB.w * b11.x;
        acc1.y += wB.x * b00.y + wB.y * b01.y + wB.z * b10.y + wB.w * b11.y;
        acc1.z += wB.x * b00.z + wB.y * b01.z + wB.z * b10.z + wB.w * b11.z;
        acc1.w += wB.x * b00.w + wB.y * b01.w + wB.z * b10.w + wB.w * b11.w;

        acc2.x += wC.x * c00.x + wC.y * c01.x + wC.z * c10.x + wC.w * c11.x;
        acc2.y += wC.x * c00.y + wC.y * c01.y + wC.z * c10.y + wC.w * c11.y;
        acc2.z += wC.x * c00.z + wC.y * c01.z + wC.z * c10.z + wC.w * c11.z;
        acc2.w += wC.x * c00.w + wC.y * c01.w + wC.z * c10.w + wC.w * c11.w;
    }
    for (; p < total; p += 8) {
        const int4   o = sOff[p];
        const float4 w = sWt[p];
        const float4 f00 = *(const float4*)(pb + o.x);
        const float4 f01 = *(const float4*)(pb + o.y);
        const float4 f10 = *(const float4*)(pb + o.z);
        const float4 f11 = *(const float4*)(pb + o.w);
        acc0.x += w.x * f00.x + w.y * f01.x + w.z * f10.x + w.w * f11.x;
        acc0.y += w.x * f00.y + w.y * f01.y + w.z * f10.y + w.w * f11.y;
        acc0.z += w.x * f00.z + w.y * f01.z + w.z * f10.z + w.w * f11.z;
        acc0.w += w.x * f00.w + w.y * f01.w + w.z * f10.w + w.w * f11.w;
    }

    acc0.x += acc1.x + acc2.x;
    acc0.y += acc1.y + acc2.y;
    acc0.z += acc1.z + acc2.z;
    acc0.w += acc1.w + acc2.w;

    // Deterministic cross-warp reduction
    ((float4*)part)[wz * 32 + lane] = acc0;
    __syncthreads();

    if (tid < C_) {
        float ssum = 0.0f;
        #pragma unroll
        for (int w = 0; w < 8; ++w) ssum += part[w * C_ + tid];
        out[n * C_ + tid] = ssum * (1.0f / 324.0f);
    }
}

extern "C" void kernel_launch(void* const* d_in, const int* in_sizes, int n_in,
                              void* d_out, int out_size) {
    const float* fm   = (const float*)d_in[0];
    const float* rois = (const float*)d_in[1];
    float* out        = (float*)d_out;
    const int nroi    = in_sizes[1] / 5;

    rroi_kernel<<<nroi, 256>>>(fm, rois, out, nroi);
}

// round 9
// speedup vs baseline: 1.2502x; 1.0744x over previous
#include <cuda_runtime.h>

// Problem constants (fixed by setup_inputs)
#define B_    4
#define H_    64
#define W_    96
#define CH_   1152      // K*K*128
#define WCH_  (W_ * CH_)
#define C_    128
#define S_    6
#define IMW_  1536.0f
#define IMH_  1024.0f

// Block = 1 ROI, 256 threads = 8 warps; each lane owns 4 channels (float4).
// Compact 16B descriptor per valid sample: {ox|flags, wy0, wy1, wx0}.
//   taps = ox + {0, dx, dy, dy+dx}; dx = (flags&1)?CH:0, dy = (flags&2)?WCH:0
//   weights rebuilt in-loop; zero-padded descriptors give all-zero weights.
// Loop unrolled x2 with next-iteration descriptor prefetch (LDS hidden
// behind LDG/FMA), no tail branch (padded to multiple of 16).

__global__ __launch_bounds__(256, 4) void rroi_kernel(
    const float* __restrict__ fm,
    const float* __restrict__ rois,
    float* __restrict__ out,
    int nroi)
{
    const int n = blockIdx.x;
    if (n >= nroi) return;

    const int tid  = threadIdx.x;
    const int wz   = tid >> 5;
    const int lane = tid & 31;

    // raw (uncompacted) descriptor tables
    __shared__ float tyw0[18], tyw1[18], txw0[18], txw1[18];
    __shared__ int   tyr0[18], tyr1[18], txc0[18], txc1[18];
    __shared__ int   tyv[18], txv[18];
    // compacted lists
    __shared__ int   cYr0[18], cYr1[18], cYch[18];
    __shared__ float cYw0[18], cYw1[18];
    __shared__ int   cXc0[18], cXc1[18], cXch[18];
    __shared__ float cXw0[18];
    __shared__ int   sNy, sNx;
    // per-pair compact descriptors (padded)
    __shared__ int4  sDesc[352];
    __shared__ float part[8 * C_];

    // ROI params (broadcast loads)
    const float rb  = rois[n * 5 + 0];
    const float rx1 = rois[n * 5 + 1];
    const float ry1 = rois[n * 5 + 2];
    const float rx2 = rois[n * 5 + 3];
    const float ry2 = rois[n * 5 + 4];

    const int   b   = (int)rb;
    const float bx1 = rx1 / IMW_;
    const float by1 = ry1 / IMH_;
    const float bx2 = rx2 / IMW_;
    const float by2 = ry2 / IMH_;

    const float bin_w = (bx2 - bx1) / 3.0f;
    const float bin_h = by2 - by1 / 3.0f;      // reference bug, replicated

    // Phase 1: 18 y-descriptors (threads 0-17), 18 x-descriptors (threads 64-81)
    if (tid < 18) {
        const int d  = tid;
        const int ih = d / 6;
        const int sy = d - ih * 6;
        const float cy1 = by1 + (float)ih * bin_h;
        const float cy2 = by1 + (float)(ih + 1) * bin_h;
        const float ysv = cy1 * (float)(H_ - 1)
                        + (float)sy * ((cy2 - cy1) * (float)(H_ - 1) / (float)(S_ - 1));
        const int valid = (ysv >= 0.0f) && (ysv <= (float)(H_ - 1));
        const float y0f = floorf(ysv);
        const float ly  = ysv - y0f;
        int i0 = (int)y0f;
        i0 = i0 < 0 ? 0 : (i0 > H_ - 1 ? H_ - 1 : i0);
        int i1 = i0 + 1 > H_ - 1 ? H_ - 1 : i0 + 1;
        tyv[d]  = valid;
        tyr0[d] = i0 * WCH_;
        tyr1[d] = i1 * WCH_;
        tyw0[d] = 1.0f - ly;
        tyw1[d] = ly;
    } else if (tid >= 64 && tid < 82) {
        const int d  = tid - 64;
        const int iw = d / 6;
        const int sx = d - iw * 6;
        const float cx1 = bx1 + (float)iw * bin_w;
        const float cx2 = bx1 + (float)(iw + 1) * bin_h;   // reference bug, replicated
        const float xsv = cx1 * (float)(W_ - 1)
                        + (float)sx * ((cx2 - cx1) * (float)(W_ - 1) / (float)(S_ - 1));
        const int valid = (xsv >= 0.0f) && (xsv <= (float)(W_ - 1));
        const float x0f = floorf(xsv);
        const float lx  = xsv - x0f;
        int i0 = (int)x0f;
        i0 = i0 < 0 ? 0 : (i0 > W_ - 1 ? W_ - 1 : i0);
        int i1 = i0 + 1 > W_ - 1 ? W_ - 1 : i0 + 1;
        txv[d]  = valid;
        txc0[d] = i0 * CH_;
        txc1[d] = i1 * CH_;
        txw0[d] = 1.0f - lx;
    }
    __syncthreads();

    // Phase 2: compact valid descriptors (two threads in different warps)
    if (tid == 0) {
        int c = 0;
        #pragma unroll
        for (int d = 0; d < 18; ++d) {
            if (tyv[d]) {
                cYr0[c] = tyr0[d];
                cYr1[c] = tyr1[d];
                cYw0[c] = tyw0[d];
                cYw1[c] = tyw1[d];
                cYch[c] = (d / 6) * (3 * C_);   // ih*3*C
                ++c;
            }
        }
        sNy = c;
    } else if (tid == 32) {
        int c = 0;
        #pragma unroll
        for (int d = 0; d < 18; ++d) {
            if (txv[d]) {
                cXc0[c] = txc0[d];
                cXc1[c] = txc1[d];
                cXw0[c] = txw0[d];
                cXch[c] = (d / 6) * C_;         // iw*C
                ++c;
            }
        }
        sNx = c;
    }
    __syncthreads();

    const int ny = sNy, nx = sNx;
    const int total = ny * nx;
    const int totp  = (total + 15) & ~15;   // padded loop bound (mult of 16)

    // Phase 3: build compact descriptors; zero-pad [total, totp+16)
    for (int p = tid; p < totp + 16; p += 256) {
        int4 d;
        if (p < total) {
            const int yi = p / nx;
            const int xi = p - yi * nx;
            const int ox = cYr0[yi] + cXc0[xi] + cYch[yi] + cXch[xi];
            const int fl = ((cYr1[yi] != cYr0[yi]) ? 2 : 0)
                         | ((cXc1[xi] != cXc0[xi]) ? 1 : 0);
            d.x = ox | fl;                      // ox is a multiple of 128
            d.y = __float_as_int(cYw0[yi]);     // wy0
            d.z = __float_as_int(cYw1[yi]);     // wy1
            d.w = __float_as_int(cXw0[xi]);     // wx0
        } else {
            d = make_int4(0, 0, 0, 0);          // all-zero weights -> no contribution
        }
        sDesc[p] = d;
    }
    __syncthreads();

    // Main loop (unrolled x2, descriptor prefetch): 8 warps stride samples.
    const float* pb = fm + (size_t)b * (H_ * W_ * CH_) + lane * 4;

    float4 acc0 = make_float4(0.0f, 0.0f, 0.0f, 0.0f);
    float4 acc1 = make_float4(0.0f, 0.0f, 0.0f, 0.0f);

    int4 dA = sDesc[wz];
    int4 dB = sDesc[wz + 8];

    for (int p = wz; p < totp; p += 16) {
        // decode A
        const int oxA = dA.x & ~3;
        const int dyA = (dA.x & 2) ? WCH_ : 0;
        const int dxA = (dA.x & 1) ? CH_  : 0;
        const float wy0A = __int_as_float(dA.y);
        const float wy1A = __int_as_float(dA.z);
        const float wx0A = __int_as_float(dA.w);
        const float wx1A = 1.0f - wx0A;
        // decode B
        const int oxB = dB.x & ~3;
        const int dyB = (dB.x & 2) ? WCH_ : 0;
        const int dxB = (dB.x & 1) ? CH_  : 0;
        const float wy0B = __int_as_float(dB.y);
        const float wy1B = __int_as_float(dB.z);
        const float wx0B = __int_as_float(dB.w);
        const float wx1B = 1.0f - wx0B;

        // 8 independent LDG.128 in flight
        const float4 a00 = *(const float4*)(pb + oxA);
        const float4 a01 = *(const float4*)(pb + oxA + dxA);
        const float4 a10 = *(const float4*)(pb + oxA + dyA);
        const float4 a11 = *(const float4*)(pb + oxA + dyA + dxA);
        const float4 b00 = *(const float4*)(pb + oxB);
        const float4 b01 = *(const float4*)(pb + oxB + dxB);
        const float4 b10 = *(const float4*)(pb + oxB + dyB);
        const float4 b11 = *(const float4*)(pb + oxB + dyB + dxB);

        // prefetch next iteration's descriptors (LDS overlaps LDG latency)
        const int4 nA = sDesc[p + 16];
        const int4 nB = sDesc[p + 24];

        const float w00A = wy0A * wx0A, w01A = wy0A * wx1A;
        const float w10A = wy1A * wx0A, w11A = wy1A * wx1A;
        const float w00B = wy0B * wx0B, w01B = wy0B * wx1B;
        const float w10B = wy1B * wx0B, w11B = wy1B * wx1B;

        acc0.x += w00A * a00.x + w01A * a01.x + w10A * a10.x + w11A * a11.x;
        acc0.y += w00A * a00.y + w01A * a01.y + w10A * a10.y + w11A * a11.y;
        acc0.z += w00A * a00.z + w01A * a01.z + w10A * a10.z + w11A * a11.z;
        acc0.w += w00A * a00.w + w01A * a01.w + w10A * a10.w + w11A * a11.w;

        acc1.x += w00B * b00.x + w01B * b01.x + w10B * b10.x + w11B * b11.x;
        acc1.y += w00B * b00.y + w01B * b01.y + w10B * b10.y + w11B * b11.y;
        acc1.z += w00B * b00.z + w01B * b01.z + w10B * b10.z + w11B * b11.z;
        acc1.w += w00B * b00.w + w01B * b01.w + w10B * b10.w + w11B * b11.w;

        dA = nA;
        dB = nB;
    }

    acc0.x += acc1.x; acc0.y += acc1.y; acc0.z += acc1.z; acc0.w += acc1.w;

    // Deterministic cross-warp reduction
    ((float4*)part)[wz * 32 + lane] = acc0;
    __syncthreads();

    if (tid < C_) {
        float ssum = 0.0f;
        #pragma unroll
        for (int w = 0; w < 8; ++w) ssum += part[w * C_ + tid];
        out[n * C_ + tid] = ssum * (1.0f / 324.0f);
    }
}

extern "C" void kernel_launch(void* const* d_in, const int* in_sizes, int n_in,
                              void* d_out, int out_size) {
    const float* fm   = (const float*)d_in[0];
    const float* rois = (const float*)d_in[1];
    float* out        = (float*)d_out;
    const int nroi    = in_sizes[1] / 5;

    rroi_kernel<<<nroi, 256>>>(fm, rois, out, nroi);
}